// round 9
// baseline (speedup 1.0000x reference)
#include <cuda_runtime.h>
#include <cuda_bf16.h>
#include <math.h>
#include <stdint.h>

#define NN 4096
#define MEM 512
#define HS 4224   // padded row count for h_split (level tiles read past last node)

// ---------------- scratch (static device globals; no allocation) ----------------
__device__ float g_ifou[NN * 2048];
__device__ float g_c[(NN + 1) * MEM];
__device__ float g_h[(NN + 1) * MEM];
__device__ float g_iou[683 * 1536];
__device__ float g_fw[(NN + 1) * MEM];
// pre-split (hi,mid) bf16x2 pairs, packed per k-pair
__device__ uint2 g_wxs[256 * 2048];   // Wx split [kp][n]
__device__ uint2 g_wss[256 * 1536];   // Ws split [kp][n]
__device__ uint2 g_wfs[256 * 512];    // Wf split [kp][n]
__device__ uint2 g_isp[256 * 4096];   // inputs split, transposed [kp][row]
__device__ uint2 g_hsp[256 * HS];     // h split, transposed [kp][node]

__device__ __forceinline__ float sigmoidf_(float x) { return 1.0f / (1.0f + expf(-x)); }

__device__ __forceinline__ int child_id(int p, int k) {
    int c = 4 * p - 12289 + k;
    return c < 0 ? NN : c;
}

// ---------------- bf16 split helpers ----------------
__device__ __forceinline__ uint2 split_pack(float x0, float x1) {
    __nv_bfloat162 h = __floats2bfloat162_rn(x0, x1);
    float r0 = x0 - __bfloat162float(h.x);
    float r1 = x1 - __bfloat162float(h.y);
    __nv_bfloat162 m = __floats2bfloat162_rn(r0, r1);
    uint2 o;
    o.x = *reinterpret_cast<uint32_t*>(&h);
    o.y = *reinterpret_cast<uint32_t*>(&m);
    return o;
}

__device__ __forceinline__ void mma16(float* d, const uint32_t* a, const uint32_t* b) {
    asm volatile(
        "mma.sync.aligned.m16n8k16.row.col.f32.bf16.bf16.f32 "
        "{%0,%1,%2,%3}, {%4,%5,%6,%7}, {%8,%9}, {%0,%1,%2,%3};"
        : "+f"(d[0]), "+f"(d[1]), "+f"(d[2]), "+f"(d[3])
        : "r"(a[0]), "r"(a[1]), "r"(a[2]), "r"(a[3]), "r"(b[0]), "r"(b[1]));
}

__device__ __forceinline__ void cpa8(uint32_t dst, const void* src) {
    asm volatile("cp.async.ca.shared.global [%0], [%1], 8;" :: "r"(dst), "l"(src));
}
__device__ __forceinline__ void cpa16(uint32_t dst, const void* src) {
    asm volatile("cp.async.cg.shared.global [%0], [%1], 16;" :: "r"(dst), "l"(src));
}
__device__ __forceinline__ void cpa_commit() {
    asm volatile("cp.async.commit_group;" ::: "memory");
}
__device__ __forceinline__ void cpa_wait1() {
    asm volatile("cp.async.wait_group 1;" ::: "memory");
}
__device__ __forceinline__ void cpa_wait0() {
    asm volatile("cp.async.wait_group 0;" ::: "memory");
}

// ---------------- smem layout ----------------
constexpr int STAGES = 2;
constexpr int KC = 32;          // k per chunk
constexpr int KPC = KC / 2;     // 16 k-pairs
constexpr int NCH = 512 / KC;   // 16 chunks
__device__ __forceinline__ int a_off(int st, int kp, int row) {
    return st * (KPC * 128) + kp * 128 + (row ^ ((kp & 3) << 2));
}
__device__ __forceinline__ int b_off(int st, int kp, int col) {
    return STAGES * (KPC * 128) + st * (KPC * 128) + kp * 128 + (col ^ ((kp & 3) << 2));
}
constexpr int SMEM_BYTES = 2 * STAGES * KPC * 128 * 8;  // 64 KB

// ======================= async bf16-split GEMM body =======================
// C[bm:bm+128, bn:bn+128] for C = A[M,512] @ B[512,Ncol] + bias
// MODE 0: A from pre-split global Asp [kp][AS rows], row offset abase (cp.async)
// MODE 1: A row m = sum of 4 child h-rows (fp32 H) of node pbase+m (reg gather)
template <int MODE>
__device__ __forceinline__
void gemm_body(const uint2* __restrict__ Asp, int AS, int abase,
               const float* __restrict__ H, int pbase,
               const uint2* __restrict__ Bsp,
               const float* __restrict__ bias, float* __restrict__ C,
               int M, int Ncol, int bm, int bn) {
    extern __shared__ uint2 sm2[];
    const uint32_t sbase = (uint32_t)__cvta_generic_to_shared(sm2);
    const int tid = threadIdx.x;
    const int wid = tid >> 5;
    const int lid = tid & 31;
    const int wm = (wid & 1) * 64;
    const int wn = (wid >> 1) * 32;
    const int g = lid >> 2;
    const int c3 = lid & 3;

    // staging assignments
    const int srow = tid & 127;          // A row
    const int skpb = (tid >> 7) * 8;     // A: 8 kp per thread
    const int scol = (tid & 63) * 2;     // B: col pair
    const int skp4 = (tid >> 6) * 4;     // B: 4 kp per thread

    auto issueStage = [&](int ch, int st) {
        if (MODE == 0) {
#pragma unroll
            for (int i = 0; i < 8; ++i) {
                int kp = skpb + i;
                const uint2* src = Asp + (size_t)(ch * KPC + kp) * AS + abase + bm + srow;
                cpa8(sbase + (uint32_t)a_off(st, kp, srow) * 8, src);
            }
        } else {
            int gr = bm + srow;
            float v[16];
#pragma unroll
            for (int j = 0; j < 16; ++j) v[j] = 0.f;
            if (gr < M) {
                int p = pbase + gr;
                int kb = ch * KC + skpb * 2;
#pragma unroll
                for (int kk = 0; kk < 4; ++kk) {
                    int cid = child_id(p, kk);
                    const float* hp = H + (size_t)cid * 512 + kb;
#pragma unroll
                    for (int j = 0; j < 4; ++j) {
                        float4 t = *reinterpret_cast<const float4*>(hp + 4 * j);
                        v[4 * j + 0] += t.x; v[4 * j + 1] += t.y;
                        v[4 * j + 2] += t.z; v[4 * j + 3] += t.w;
                    }
                }
            }
#pragma unroll
            for (int i = 0; i < 8; ++i)
                sm2[a_off(st, skpb + i, srow)] = split_pack(v[2 * i], v[2 * i + 1]);
        }
#pragma unroll
        for (int i = 0; i < 4; ++i) {
            int kp = skp4 + i;
            const uint2* src = Bsp + (size_t)(ch * KPC + kp) * Ncol + bn + scol;
            cpa16(sbase + (uint32_t)b_off(st, kp, scol) * 8, src);
        }
    };

    float acc[4][4][4];
#pragma unroll
    for (int mt = 0; mt < 4; ++mt)
#pragma unroll
        for (int nt = 0; nt < 4; ++nt)
#pragma unroll
            for (int i = 0; i < 4; ++i) acc[mt][nt][i] = 0.f;

    auto compute = [&](int st) {
#pragma unroll
        for (int s = 0; s < 2; ++s) {
            // phase 1: load Ah + Bh, run Ah*Bh (16 independent MMAs)
            uint32_t ah[4][4], aml[4][4];
            uint32_t bh[4][2], bml[4][2];
#pragma unroll
            for (int mt = 0; mt < 4; ++mt) {
                int r0 = wm + mt * 16 + g;
                uint2 t;
                t = sm2[a_off(st, s * 8 + c3, r0)];          ah[mt][0] = t.x; aml[mt][0] = t.y;
                t = sm2[a_off(st, s * 8 + c3, r0 + 8)];      ah[mt][1] = t.x; aml[mt][1] = t.y;
                t = sm2[a_off(st, s * 8 + c3 + 4, r0)];      ah[mt][2] = t.x; aml[mt][2] = t.y;
                t = sm2[a_off(st, s * 8 + c3 + 4, r0 + 8)];  ah[mt][3] = t.x; aml[mt][3] = t.y;
            }
#pragma unroll
            for (int nt = 0; nt < 4; ++nt) {
                int n0 = wn + nt * 8 + g;
                uint2 t;
                t = sm2[b_off(st, s * 8 + c3, n0)];      bh[nt][0] = t.x; bml[nt][0] = t.y;
                t = sm2[b_off(st, s * 8 + c3 + 4, n0)];  bh[nt][1] = t.x; bml[nt][1] = t.y;
            }
            // term-major ordering: 16 independent MMAs between accumulator reuses
#pragma unroll
            for (int mt = 0; mt < 4; ++mt)
#pragma unroll
                for (int nt = 0; nt < 4; ++nt)
                    mma16(acc[mt][nt], ah[mt], bh[nt]);
#pragma unroll
            for (int mt = 0; mt < 4; ++mt)
#pragma unroll
                for (int nt = 0; nt < 4; ++nt)
                    mma16(acc[mt][nt], ah[mt], bml[nt]);
#pragma unroll
            for (int mt = 0; mt < 4; ++mt)
#pragma unroll
                for (int nt = 0; nt < 4; ++nt)
                    mma16(acc[mt][nt], aml[mt], bh[nt]);
        }
    };

    // 2-stage pipeline: one chunk in flight while computing the previous
    issueStage(0, 0);
    cpa_commit();
    for (int ch = 0; ch < NCH; ++ch) {
        int nx = ch + 1;
        if (nx < NCH) {
            issueStage(nx, nx & 1);
            cpa_commit();
            cpa_wait1();          // chunk ch complete (nx may be in flight)
        } else {
            cpa_wait0();
        }
        __syncthreads();          // visibility of chunk ch to all warps
        compute(ch & 1);
        __syncthreads();          // protect buffer ch&1 before it is refilled
    }

    // epilogue
#pragma unroll
    for (int mt = 0; mt < 4; ++mt) {
        int r = bm + wm + mt * 16 + g;
        int r2 = r + 8;
#pragma unroll
        for (int nt = 0; nt < 4; ++nt) {
            int col = bn + wn + nt * 8 + 2 * c3;
            float b0 = bias[col], b1 = bias[col + 1];
            if (r < M) {
                float2 o = make_float2(acc[mt][nt][0] + b0, acc[mt][nt][1] + b1);
                *reinterpret_cast<float2*>(&C[(size_t)r * Ncol + col]) = o;
            }
            if (r2 < M) {
                float2 o = make_float2(acc[mt][nt][2] + b0, acc[mt][nt][3] + b1);
                *reinterpret_cast<float2*>(&C[(size_t)r2 * Ncol + col]) = o;
            }
        }
    }
}

// plain single-GEMM kernel (used for ifou)
template <int MODE>
__global__ __launch_bounds__(256, 2)
void gemm_async(const uint2* __restrict__ Asp, int AS, int abase,
                const float* __restrict__ H, int pbase,
                const uint2* __restrict__ Bsp,
                const float* __restrict__ bias, float* __restrict__ C,
                int M, int Ncol) {
    gemm_body<MODE>(Asp, AS, abase, H, pbase, Bsp, bias, C, M, Ncol,
                    blockIdx.y * 128, blockIdx.x * 128);
}

// dual kernel: z=0 -> iou GEMM (MODE1 gather), z=1 -> fw GEMM (MODE0 dense)
__global__ __launch_bounds__(256, 2)
void gemm_dual(const float* __restrict__ H, int pbase,
               const uint2* __restrict__ wss, const float* __restrict__ bs,
               float* __restrict__ iou, int M1,
               const uint2* __restrict__ hsp, int abase,
               const uint2* __restrict__ wfs, const float* __restrict__ bf,
               float* __restrict__ fwout, int M0) {
    if (blockIdx.z == 0) {
        if ((int)blockIdx.x >= 12 || (int)(blockIdx.y * 128) >= M1) return;
        gemm_body<1>(nullptr, 0, 0, H, pbase, wss, bs, iou, M1, 1536,
                     blockIdx.y * 128, blockIdx.x * 128);
    } else {
        if ((int)blockIdx.x >= 4 || (int)(blockIdx.y * 128) >= M0) return;
        gemm_body<0>(hsp, HS, abase, nullptr, 0, wfs, bf, fwout, M0, 512,
                     blockIdx.y * 128, blockIdx.x * 128);
    }
}

// ---------------- pre-split kernels ----------------
// all three weight matrices in one launch, flattened over 4096 columns
__global__ void split_w_all(const float* __restrict__ Wx, const float* __restrict__ Ws,
                            const float* __restrict__ Wf,
                            uint2* __restrict__ wxs, uint2* __restrict__ wss,
                            uint2* __restrict__ wfs) {
    int n = blockIdx.x * 256 + threadIdx.x;   // 0..4095
    int kp = blockIdx.y;                      // 0..255
    const float* W; uint2* out; int Ncol; int nn;
    if (n < 2048)      { W = Wx; out = wxs; Ncol = 2048; nn = n; }
    else if (n < 3584) { W = Ws; out = wss; Ncol = 1536; nn = n - 2048; }
    else               { W = Wf; out = wfs; Ncol = 512;  nn = n - 3584; }
    float a = W[(size_t)(2 * kp) * Ncol + nn];
    float b = W[(size_t)(2 * kp + 1) * Ncol + nn];
    out[(size_t)kp * Ncol + nn] = split_pack(a, b);
}

// inputs[4096][512] -> isp[kp][4096] (smem transpose)
__global__ void split_in_kernel(const float* __restrict__ in, uint2* __restrict__ out) {
    __shared__ float2 tile[32][33];
    int row = blockIdx.x * 32 + threadIdx.y;
    int kp = blockIdx.y * 32 + threadIdx.x;
    tile[threadIdx.y][threadIdx.x] = *reinterpret_cast<const float2*>(in + (size_t)row * 512 + 2 * kp);
    __syncthreads();
    int orow = blockIdx.x * 32 + threadIdx.x;
    int okp = blockIdx.y * 32 + threadIdx.y;
    float2 v = tile[threadIdx.x][threadIdx.y];
    out[(size_t)okp * 4096 + orow] = split_pack(v.x, v.y);
}

// ---------------- elementwise kernels ----------------
__global__ void init_kernel(float* cbuf, float* hbuf) {
    int j = threadIdx.x;
    cbuf[(size_t)NN * MEM + j] = 0.f;
    hbuf[(size_t)NN * MEM + j] = 0.f;
}

__global__ void leaf_kernel(const float* __restrict__ ifou, const float* __restrict__ bs,
                            float* __restrict__ cbuf, float* __restrict__ hbuf,
                            uint2* __restrict__ hsp) {
    int p = blockIdx.x;
    int j = threadIdx.x;
    const float* r = ifou + (size_t)p * 2048;
    float iv = sigmoidf_(r[j] + bs[j]);
    float ov = sigmoidf_(r[1024 + j] + bs[512 + j]);
    float uv = tanhf(r[1536 + j] + bs[1024 + j]);
    float c = iv * uv;
    float h = ov * tanhf(c);
    cbuf[(size_t)p * MEM + j] = c;
    hbuf[(size_t)p * MEM + j] = h;
    float hn = __shfl_down_sync(0xffffffffu, h, 1);
    if ((j & 1) == 0) hsp[(size_t)(j >> 1) * HS + p] = split_pack(h, hn);
}

__global__ void combine_kernel(const float* __restrict__ ifou, const float* __restrict__ iou,
                               const float* __restrict__ fw, float* __restrict__ cbuf,
                               float* __restrict__ hbuf, uint2* __restrict__ hsp, int base) {
    int m = blockIdx.x;
    int j = threadIdx.x;
    int p = base + m;
    const float* r = ifou + (size_t)p * 2048;
    float ix = r[j], fx = r[512 + j], ox = r[1024 + j], ux = r[1536 + j];
    float iv = sigmoidf_(ix + iou[(size_t)m * 1536 + j]);
    float ov = sigmoidf_(ox + iou[(size_t)m * 1536 + 512 + j]);
    float uv = tanhf(ux + iou[(size_t)m * 1536 + 1024 + j]);
    float c = iv * uv;
#pragma unroll
    for (int k = 0; k < 4; ++k) {
        int cid = child_id(p, k);
        float f = sigmoidf_(fw[(size_t)cid * MEM + j] + fx);
        c += f * cbuf[(size_t)cid * MEM + j];
    }
    float h = ov * tanhf(c);
    cbuf[(size_t)p * MEM + j] = c;
    hbuf[(size_t)p * MEM + j] = h;
    float hn = __shfl_down_sync(0xffffffffu, h, 1);
    if ((j & 1) == 0) hsp[(size_t)(j >> 1) * HS + p] = split_pack(h, hn);
}

__global__ void copyout_kernel(const float* __restrict__ hbuf, float* __restrict__ out) {
    out[threadIdx.x] = hbuf[(size_t)(NN - 1) * MEM + threadIdx.x];
}

// ---------------- launch ----------------
extern "C" void kernel_launch(void* const* d_in, const int* in_sizes, int n_in,
                              void* d_out, int out_size) {
    const float* inputs = (const float*)d_in[0];
    const float* Wx     = (const float*)d_in[1];
    const float* bx     = (const float*)d_in[2];
    const float* Ws     = (const float*)d_in[3];
    const float* bs     = (const float*)d_in[4];
    const float* Wf     = (const float*)d_in[5];
    const float* bf     = (const float*)d_in[6];
    float* out = (float*)d_out;

    float *ifou, *cbuf, *hbuf, *iou, *fw;
    uint2 *wxs, *wss, *wfs, *isp, *hsp;
    cudaGetSymbolAddress((void**)&ifou, g_ifou);
    cudaGetSymbolAddress((void**)&cbuf, g_c);
    cudaGetSymbolAddress((void**)&hbuf, g_h);
    cudaGetSymbolAddress((void**)&iou, g_iou);
    cudaGetSymbolAddress((void**)&fw, g_fw);
    cudaGetSymbolAddress((void**)&wxs, g_wxs);
    cudaGetSymbolAddress((void**)&wss, g_wss);
    cudaGetSymbolAddress((void**)&wfs, g_wfs);
    cudaGetSymbolAddress((void**)&isp, g_isp);
    cudaGetSymbolAddress((void**)&hsp, g_hsp);

    cudaFuncSetAttribute(gemm_async<0>, cudaFuncAttributeMaxDynamicSharedMemorySize, SMEM_BYTES);
    cudaFuncSetAttribute(gemm_dual, cudaFuncAttributeMaxDynamicSharedMemorySize, SMEM_BYTES);

    init_kernel<<<1, 512>>>(cbuf, hbuf);

    // pre-split constants
    split_w_all<<<dim3(16, 256), 256>>>(Wx, Ws, Wf, wxs, wss, wfs);
    split_in_kernel<<<dim3(4096 / 32, 256 / 32), dim3(32, 32)>>>(inputs, isp);

    // ifou = inputs @ Wx + bx
    gemm_async<0><<<dim3(2048 / 128, 4096 / 128), 256, SMEM_BYTES>>>(
        isp, 4096, 0, nullptr, 0, wxs, bx, ifou, NN, 2048);

    leaf_kernel<<<3072, 512>>>(ifou, bs, cbuf, hbuf, hsp);

    static const int baseArr[6] = {3072, 3755, 4011, 4075, 4091, 4095};
    static const int cntArr[6]  = {683, 256, 64, 16, 4, 1};
    int prevBase = 0, prevCnt = 3072;
    for (int l = 0; l < 6; ++l) {
        int m = cntArr[l], base = baseArr[l];
        int gy = (m + 127) / 128;
        int gy0 = (prevCnt + 127) / 128;
        int gymax = gy > gy0 ? gy : gy0;
        // z=0: iou_l = (sum child h) @ Ws + bs ; z=1: fw of previous level
        gemm_dual<<<dim3(12, gymax, 2), 256, SMEM_BYTES>>>(
            hbuf, base, wss, bs, iou, m,
            hsp, prevBase, wfs, bf, fw + (size_t)prevBase * 512, prevCnt);
        combine_kernel<<<m, 512>>>(ifou, iou, fw, cbuf, hbuf, hsp, base);
        prevBase = base;
        prevCnt = m;
    }

    copyout_kernel<<<1, 512>>>(hbuf, out);
}

// round 11
// speedup vs baseline: 1.2124x; 1.2124x over previous
#include <cuda_runtime.h>
#include <cuda_bf16.h>
#include <math.h>
#include <stdint.h>

#define NN 4096
#define MEM 512
#define HS 4224   // padded row count for h_split (level tiles read past last node)

// ---------------- scratch (static device globals; no allocation) ----------------
__device__ float g_ifou[NN * 2048];
__device__ float g_c[(NN + 1) * MEM];
__device__ float g_h[(NN + 1) * MEM];
__device__ float g_iou[683 * 1536];
__device__ float g_fw[(NN + 1) * MEM];
// pre-split (hi,mid) bf16x2 pairs, packed per k-pair
__device__ uint2 g_wxs[256 * 2048];   // Wx split [kp][n]
__device__ uint2 g_wss[256 * 1536];   // Ws split [kp][n]
__device__ uint2 g_wfs[256 * 512];    // Wf split [kp][n]
__device__ uint2 g_isp[256 * 4096];   // inputs split, transposed [kp][row]
__device__ uint2 g_hsp[256 * HS];     // h split, transposed [kp][node]

__device__ __forceinline__ float sigmoidf_(float x) { return 1.0f / (1.0f + expf(-x)); }

__device__ __forceinline__ int child_id(int p, int k) {
    int c = 4 * p - 12289 + k;
    return c < 0 ? NN : c;
}

// ---------------- bf16 split helpers ----------------
__device__ __forceinline__ uint2 split_pack(float x0, float x1) {
    __nv_bfloat162 h = __floats2bfloat162_rn(x0, x1);
    float r0 = x0 - __bfloat162float(h.x);
    float r1 = x1 - __bfloat162float(h.y);
    __nv_bfloat162 m = __floats2bfloat162_rn(r0, r1);
    uint2 o;
    o.x = *reinterpret_cast<uint32_t*>(&h);
    o.y = *reinterpret_cast<uint32_t*>(&m);
    return o;
}

__device__ __forceinline__ void mma16(float* d, const uint32_t* a, const uint32_t* b) {
    asm volatile(
        "mma.sync.aligned.m16n8k16.row.col.f32.bf16.bf16.f32 "
        "{%0,%1,%2,%3}, {%4,%5,%6,%7}, {%8,%9}, {%0,%1,%2,%3};"
        : "+f"(d[0]), "+f"(d[1]), "+f"(d[2]), "+f"(d[3])
        : "r"(a[0]), "r"(a[1]), "r"(a[2]), "r"(a[3]), "r"(b[0]), "r"(b[1]));
}

__device__ __forceinline__ void cpa8(uint32_t dst, const void* src) {
    asm volatile("cp.async.ca.shared.global [%0], [%1], 8;" :: "r"(dst), "l"(src));
}
__device__ __forceinline__ void cpa16(uint32_t dst, const void* src) {
    asm volatile("cp.async.cg.shared.global [%0], [%1], 16;" :: "r"(dst), "l"(src));
}
__device__ __forceinline__ void cpa_commit() {
    asm volatile("cp.async.commit_group;" ::: "memory");
}
__device__ __forceinline__ void cpa_wait1() {
    asm volatile("cp.async.wait_group 1;" ::: "memory");
}
__device__ __forceinline__ void cpa_wait0() {
    asm volatile("cp.async.wait_group 0;" ::: "memory");
}

// ---------------- smem layout ----------------
constexpr int STAGES = 3;
constexpr int KC = 64;          // k per chunk
constexpr int KPC = KC / 2;     // 32 k-pairs
constexpr int NCH = 512 / KC;   // 8 chunks
__device__ __forceinline__ int a_off(int st, int kp, int row) {
    return st * (KPC * 128) + kp * 128 + (row ^ ((kp & 3) << 2));
}
__device__ __forceinline__ int b_off(int st, int kp, int col) {
    return STAGES * (KPC * 128) + st * (KPC * 128) + kp * 128 + (col ^ ((kp & 3) << 2));
}
constexpr int SMEM_BYTES = 2 * STAGES * KPC * 128 * 8;  // 192 KB

// fragment set for one k16 s-block
struct Frags {
    uint32_t ah[4][4], aml[4][4];
    uint32_t bh[4][2], bml[4][2];
};

// ======================= async bf16-split GEMM body =======================
// C[bm:bm+128, bn:bn+128] for C = A[M,512] @ B[512,Ncol] + bias
// MODE 0: A from pre-split global Asp [kp][AS rows], row offset abase (cp.async)
// MODE 1: A row m = sum of 4 child h-rows (fp32 H) of node pbase+m (reg gather)
template <int MODE>
__device__ __forceinline__
void gemm_body(const uint2* __restrict__ Asp, int AS, int abase,
               const float* __restrict__ H, int pbase,
               const uint2* __restrict__ Bsp,
               const float* __restrict__ bias, float* __restrict__ C,
               int M, int Ncol, int bm, int bn) {
    extern __shared__ uint2 sm2[];
    const uint32_t sbase = (uint32_t)__cvta_generic_to_shared(sm2);
    const int tid = threadIdx.x;
    const int wid = tid >> 5;
    const int lid = tid & 31;
    const int wm = (wid & 1) * 64;
    const int wn = (wid >> 1) * 32;
    const int g = lid >> 2;
    const int c3 = lid & 3;

    // staging assignments
    const int srow = tid & 127;          // A row
    const int skpb = (tid >> 7) * 16;    // A: 16 kp per thread
    const int scol = (tid & 63) * 2;     // B: col pair
    const int skp8 = (tid >> 6) * 8;     // B: 8 kp per thread

    auto issueStage = [&](int ch, int st) {
        if (MODE == 0) {
#pragma unroll
            for (int i = 0; i < 16; ++i) {
                int kp = skpb + i;
                const uint2* src = Asp + (size_t)(ch * KPC + kp) * AS + abase + bm + srow;
                cpa8(sbase + (uint32_t)a_off(st, kp, srow) * 8, src);
            }
        } else {
            int gr = bm + srow;
            int p = pbase + gr;
#pragma unroll
            for (int half = 0; half < 2; ++half) {
                float v[16];
#pragma unroll
                for (int j = 0; j < 16; ++j) v[j] = 0.f;
                if (gr < M) {
                    int kb = ch * KC + (skpb + half * 8) * 2;
#pragma unroll
                    for (int kk = 0; kk < 4; ++kk) {
                        int cid = child_id(p, kk);
                        const float* hp = H + (size_t)cid * 512 + kb;
#pragma unroll
                        for (int j = 0; j < 4; ++j) {
                            float4 t = *reinterpret_cast<const float4*>(hp + 4 * j);
                            v[4 * j + 0] += t.x; v[4 * j + 1] += t.y;
                            v[4 * j + 2] += t.z; v[4 * j + 3] += t.w;
                        }
                    }
                }
#pragma unroll
                for (int i = 0; i < 8; ++i)
                    sm2[a_off(st, skpb + half * 8 + i, srow)] = split_pack(v[2 * i], v[2 * i + 1]);
            }
        }
#pragma unroll
        for (int i = 0; i < 8; ++i) {
            int kp = skp8 + i;
            const uint2* src = Bsp + (size_t)(ch * KPC + kp) * Ncol + bn + scol;
            cpa16(sbase + (uint32_t)b_off(st, kp, scol) * 8, src);
        }
    };

    float acc[4][4][4];
#pragma unroll
    for (int mt = 0; mt < 4; ++mt)
#pragma unroll
        for (int nt = 0; nt < 4; ++nt)
#pragma unroll
            for (int i = 0; i < 4; ++i) acc[mt][nt][i] = 0.f;

    auto loadFrag = [&](Frags& F, int st, int s) {
#pragma unroll
        for (int mt = 0; mt < 4; ++mt) {
            int r0 = wm + mt * 16 + g;
            uint2 t;
            t = sm2[a_off(st, s * 8 + c3, r0)];          F.ah[mt][0] = t.x; F.aml[mt][0] = t.y;
            t = sm2[a_off(st, s * 8 + c3, r0 + 8)];      F.ah[mt][1] = t.x; F.aml[mt][1] = t.y;
            t = sm2[a_off(st, s * 8 + c3 + 4, r0)];      F.ah[mt][2] = t.x; F.aml[mt][2] = t.y;
            t = sm2[a_off(st, s * 8 + c3 + 4, r0 + 8)];  F.ah[mt][3] = t.x; F.aml[mt][3] = t.y;
        }
#pragma unroll
        for (int nt = 0; nt < 4; ++nt) {
            int n0 = wn + nt * 8 + g;
            uint2 t;
            t = sm2[b_off(st, s * 8 + c3, n0)];      F.bh[nt][0] = t.x; F.bml[nt][0] = t.y;
            t = sm2[b_off(st, s * 8 + c3 + 4, n0)];  F.bh[nt][1] = t.x; F.bml[nt][1] = t.y;
        }
    };

    auto runMMA = [&](const Frags& F) {
#pragma unroll
        for (int mt = 0; mt < 4; ++mt)
#pragma unroll
            for (int nt = 0; nt < 4; ++nt)
                mma16(acc[mt][nt], F.ah[mt], F.bh[nt]);
#pragma unroll
        for (int mt = 0; mt < 4; ++mt)
#pragma unroll
            for (int nt = 0; nt < 4; ++nt)
                mma16(acc[mt][nt], F.ah[mt], F.bml[nt]);
#pragma unroll
        for (int mt = 0; mt < 4; ++mt)
#pragma unroll
            for (int nt = 0; nt < 4; ++nt)
                mma16(acc[mt][nt], F.aml[mt], F.bh[nt]);
    };

    // prologue: stages 0..STAGES-2 in flight
#pragma unroll
    for (int s = 0; s < STAGES - 1; ++s) {
        issueStage(s, s);
        cpa_commit();
    }

    Frags F[2];
    for (int ch = 0; ch < NCH; ++ch) {
        if (ch + STAGES - 1 < NCH) cpa_wait1(); else cpa_wait0();
        __syncthreads();
        int nx = ch + STAGES - 1;
        if (nx < NCH) {
            issueStage(nx, nx % STAGES);
            cpa_commit();
        }
        const int st = ch % STAGES;
        // 4 s-blocks, fragment double-buffered: LDS latency exposed once per chunk
        loadFrag(F[0], st, 0);
#pragma unroll
        for (int s = 0; s < 4; ++s) {
            if (s < 3) loadFrag(F[(s + 1) & 1], st, s + 1);
            runMMA(F[s & 1]);
        }
    }

    // epilogue
#pragma unroll
    for (int mt = 0; mt < 4; ++mt) {
        int r = bm + wm + mt * 16 + g;
        int r2 = r + 8;
#pragma unroll
        for (int nt = 0; nt < 4; ++nt) {
            int col = bn + wn + nt * 8 + 2 * c3;
            float b0 = bias[col], b1 = bias[col + 1];
            if (r < M) {
                float2 o = make_float2(acc[mt][nt][0] + b0, acc[mt][nt][1] + b1);
                *reinterpret_cast<float2*>(&C[(size_t)r * Ncol + col]) = o;
            }
            if (r2 < M) {
                float2 o = make_float2(acc[mt][nt][2] + b0, acc[mt][nt][3] + b1);
                *reinterpret_cast<float2*>(&C[(size_t)r2 * Ncol + col]) = o;
            }
        }
    }
}

// plain single-GEMM kernel (used for ifou)
template <int MODE>
__global__ __launch_bounds__(256, 1)
void gemm_async(const uint2* __restrict__ Asp, int AS, int abase,
                const float* __restrict__ H, int pbase,
                const uint2* __restrict__ Bsp,
                const float* __restrict__ bias, float* __restrict__ C,
                int M, int Ncol) {
    gemm_body<MODE>(Asp, AS, abase, H, pbase, Bsp, bias, C, M, Ncol,
                    blockIdx.y * 128, blockIdx.x * 128);
}

// dual kernel: z=0 -> iou GEMM (MODE1 gather), z=1 -> fw GEMM (MODE0 dense)
__global__ __launch_bounds__(256, 1)
void gemm_dual(const float* __restrict__ H, int pbase,
               const uint2* __restrict__ wss, const float* __restrict__ bs,
               float* __restrict__ iou, int M1,
               const uint2* __restrict__ hsp, int abase,
               const uint2* __restrict__ wfs, const float* __restrict__ bf,
               float* __restrict__ fwout, int M0) {
    if (blockIdx.z == 0) {
        if ((int)blockIdx.x >= 12 || (int)(blockIdx.y * 128) >= M1) return;
        gemm_body<1>(nullptr, 0, 0, H, pbase, wss, bs, iou, M1, 1536,
                     blockIdx.y * 128, blockIdx.x * 128);
    } else {
        if ((int)blockIdx.x >= 4 || (int)(blockIdx.y * 128) >= M0) return;
        gemm_body<0>(hsp, HS, abase, nullptr, 0, wfs, bf, fwout, M0, 512,
                     blockIdx.y * 128, blockIdx.x * 128);
    }
}

// ---------------- pre-split kernels ----------------
// all three weight matrices in one launch, flattened over 4096 columns
__global__ void split_w_all(const float* __restrict__ Wx, const float* __restrict__ Ws,
                            const float* __restrict__ Wf,
                            uint2* __restrict__ wxs, uint2* __restrict__ wss,
                            uint2* __restrict__ wfs) {
    int n = blockIdx.x * 256 + threadIdx.x;   // 0..4095
    int kp = blockIdx.y;                      // 0..255
    const float* W; uint2* out; int Ncol; int nn;
    if (n < 2048)      { W = Wx; out = wxs; Ncol = 2048; nn = n; }
    else if (n < 3584) { W = Ws; out = wss; Ncol = 1536; nn = n - 2048; }
    else               { W = Wf; out = wfs; Ncol = 512;  nn = n - 3584; }
    float a = W[(size_t)(2 * kp) * Ncol + nn];
    float b = W[(size_t)(2 * kp + 1) * Ncol + nn];
    out[(size_t)kp * Ncol + nn] = split_pack(a, b);
}

// inputs[4096][512] -> isp[kp][4096] (smem transpose)
__global__ void split_in_kernel(const float* __restrict__ in, uint2* __restrict__ out) {
    __shared__ float2 tile[32][33];
    int row = blockIdx.x * 32 + threadIdx.y;
    int kp = blockIdx.y * 32 + threadIdx.x;
    tile[threadIdx.y][threadIdx.x] = *reinterpret_cast<const float2*>(in + (size_t)row * 512 + 2 * kp);
    __syncthreads();
    int orow = blockIdx.x * 32 + threadIdx.x;
    int okp = blockIdx.y * 32 + threadIdx.y;
    float2 v = tile[threadIdx.x][threadIdx.y];
    out[(size_t)okp * 4096 + orow] = split_pack(v.x, v.y);
}

// ---------------- elementwise kernels ----------------
__global__ void init_kernel(float* cbuf, float* hbuf) {
    int j = threadIdx.x;
    cbuf[(size_t)NN * MEM + j] = 0.f;
    hbuf[(size_t)NN * MEM + j] = 0.f;
}

__global__ void leaf_kernel(const float* __restrict__ ifou, const float* __restrict__ bs,
                            float* __restrict__ cbuf, float* __restrict__ hbuf,
                            uint2* __restrict__ hsp) {
    int p = blockIdx.x;
    int j = threadIdx.x;
    const float* r = ifou + (size_t)p * 2048;
    float iv = sigmoidf_(r[j] + bs[j]);
    float ov = sigmoidf_(r[1024 + j] + bs[512 + j]);
    float uv = tanhf(r[1536 + j] + bs[1024 + j]);
    float c = iv * uv;
    float h = ov * tanhf(c);
    cbuf[(size_t)p * MEM + j] = c;
    hbuf[(size_t)p * MEM + j] = h;
    float hn = __shfl_down_sync(0xffffffffu, h, 1);
    if ((j & 1) == 0) hsp[(size_t)(j >> 1) * HS + p] = split_pack(h, hn);
}

__global__ void combine_kernel(const float* __restrict__ ifou, const float* __restrict__ iou,
                               const float* __restrict__ fw, float* __restrict__ cbuf,
                               float* __restrict__ hbuf, uint2* __restrict__ hsp, int base) {
    int m = blockIdx.x;
    int j = threadIdx.x;
    int p = base + m;
    const float* r = ifou + (size_t)p * 2048;
    float ix = r[j], fx = r[512 + j], ox = r[1024 + j], ux = r[1536 + j];
    float iv = sigmoidf_(ix + iou[(size_t)m * 1536 + j]);
    float ov = sigmoidf_(ox + iou[(size_t)m * 1536 + 512 + j]);
    float uv = tanhf(ux + iou[(size_t)m * 1536 + 1024 + j]);
    float c = iv * uv;
#pragma unroll
    for (int k = 0; k < 4; ++k) {
        int cid = child_id(p, k);
        float f = sigmoidf_(fw[(size_t)cid * MEM + j] + fx);
        c += f * cbuf[(size_t)cid * MEM + j];
    }
    float h = ov * tanhf(c);
    cbuf[(size_t)p * MEM + j] = c;
    hbuf[(size_t)p * MEM + j] = h;
    float hn = __shfl_down_sync(0xffffffffu, h, 1);
    if ((j & 1) == 0) hsp[(size_t)(j >> 1) * HS + p] = split_pack(h, hn);
}

__global__ void copyout_kernel(const float* __restrict__ hbuf, float* __restrict__ out) {
    out[threadIdx.x] = hbuf[(size_t)(NN - 1) * MEM + threadIdx.x];
}

// ---------------- launch ----------------
extern "C" void kernel_launch(void* const* d_in, const int* in_sizes, int n_in,
                              void* d_out, int out_size) {
    const float* inputs = (const float*)d_in[0];
    const float* Wx     = (const float*)d_in[1];
    const float* bx     = (const float*)d_in[2];
    const float* Ws     = (const float*)d_in[3];
    const float* bs     = (const float*)d_in[4];
    const float* Wf     = (const float*)d_in[5];
    const float* bf     = (const float*)d_in[6];
    float* out = (float*)d_out;

    float *ifou, *cbuf, *hbuf, *iou, *fw;
    uint2 *wxs, *wss, *wfs, *isp, *hsp;
    cudaGetSymbolAddress((void**)&ifou, g_ifou);
    cudaGetSymbolAddress((void**)&cbuf, g_c);
    cudaGetSymbolAddress((void**)&hbuf, g_h);
    cudaGetSymbolAddress((void**)&iou, g_iou);
    cudaGetSymbolAddress((void**)&fw, g_fw);
    cudaGetSymbolAddress((void**)&wxs, g_wxs);
    cudaGetSymbolAddress((void**)&wss, g_wss);
    cudaGetSymbolAddress((void**)&wfs, g_wfs);
    cudaGetSymbolAddress((void**)&isp, g_isp);
    cudaGetSymbolAddress((void**)&hsp, g_hsp);

    cudaFuncSetAttribute(gemm_async<0>, cudaFuncAttributeMaxDynamicSharedMemorySize, SMEM_BYTES);
    cudaFuncSetAttribute(gemm_dual, cudaFuncAttributeMaxDynamicSharedMemorySize, SMEM_BYTES);

    init_kernel<<<1, 512>>>(cbuf, hbuf);

    // pre-split constants
    split_w_all<<<dim3(16, 256), 256>>>(Wx, Ws, Wf, wxs, wss, wfs);
    split_in_kernel<<<dim3(4096 / 32, 256 / 32), dim3(32, 32)>>>(inputs, isp);

    // ifou = inputs @ Wx + bx
    gemm_async<0><<<dim3(2048 / 128, 4096 / 128), 256, SMEM_BYTES>>>(
        isp, 4096, 0, nullptr, 0, wxs, bx, ifou, NN, 2048);

    leaf_kernel<<<3072, 512>>>(ifou, bs, cbuf, hbuf, hsp);

    static const int baseArr[6] = {3072, 3755, 4011, 4075, 4091, 4095};
    static const int cntArr[6]  = {683, 256, 64, 16, 4, 1};
    int prevBase = 0, prevCnt = 3072;
    for (int l = 0; l < 6; ++l) {
        int m = cntArr[l], base = baseArr[l];
        int gy = (m + 127) / 128;
        int gy0 = (prevCnt + 127) / 128;
        int gymax = gy > gy0 ? gy : gy0;
        // z=0: iou_l = (sum child h) @ Ws + bs ; z=1: fw of previous level
        gemm_dual<<<dim3(12, gymax, 2), 256, SMEM_BYTES>>>(
            hbuf, base, wss, bs, iou, m,
            hsp, prevBase, wfs, bf, fw + (size_t)prevBase * 512, prevCnt);
        combine_kernel<<<m, 512>>>(ifou, iou, fw, cbuf, hbuf, hsp, base);
        prevBase = base;
        prevCnt = m;
    }

    copyout_kernel<<<1, 512>>>(hbuf, out);
}

// round 12
// speedup vs baseline: 1.2431x; 1.0253x over previous
#include <cuda_runtime.h>
#include <cuda_bf16.h>
#include <math.h>
#include <stdint.h>

#define NN 4096
#define MEM 512
#define HS 4224   // padded row count for h_split (level tiles read past last node)

// ---------------- scratch (static device globals; no allocation) ----------------
__device__ float g_ifou[NN * 2048];
__device__ float g_c[(NN + 1) * MEM];
__device__ float g_h[(NN + 1) * MEM];
__device__ float g_iou[683 * 1536];
__device__ float g_fw[(NN + 1) * MEM];
// pre-split (hi,mid) bf16x2 pairs, packed per k-pair
__device__ uint2 g_wxs[256 * 2048];   // Wx split [kp][n]
__device__ uint2 g_wss[256 * 1536];   // Ws split [kp][n]
__device__ uint2 g_wfs[256 * 512];    // Wf split [kp][n]
__device__ uint2 g_isp[256 * 4096];   // inputs split, transposed [kp][row]
__device__ uint2 g_hsp[256 * HS];     // h split, transposed [kp][node]

__device__ __forceinline__ float sigmoidf_(float x) { return 1.0f / (1.0f + expf(-x)); }

__device__ __forceinline__ int child_id(int p, int k) {
    int c = 4 * p - 12289 + k;
    return c < 0 ? NN : c;
}

// ---------------- bf16 split helpers ----------------
__device__ __forceinline__ uint2 split_pack(float x0, float x1) {
    __nv_bfloat162 h = __floats2bfloat162_rn(x0, x1);
    float r0 = x0 - __bfloat162float(h.x);
    float r1 = x1 - __bfloat162float(h.y);
    __nv_bfloat162 m = __floats2bfloat162_rn(r0, r1);
    uint2 o;
    o.x = *reinterpret_cast<uint32_t*>(&h);
    o.y = *reinterpret_cast<uint32_t*>(&m);
    return o;
}

__device__ __forceinline__ void mma16(float* d, const uint32_t* a, const uint32_t* b) {
    asm volatile(
        "mma.sync.aligned.m16n8k16.row.col.f32.bf16.bf16.f32 "
        "{%0,%1,%2,%3}, {%4,%5,%6,%7}, {%8,%9}, {%0,%1,%2,%3};"
        : "+f"(d[0]), "+f"(d[1]), "+f"(d[2]), "+f"(d[3])
        : "r"(a[0]), "r"(a[1]), "r"(a[2]), "r"(a[3]), "r"(b[0]), "r"(b[1]));
}

__device__ __forceinline__ void cpa8(uint32_t dst, const void* src) {
    asm volatile("cp.async.ca.shared.global [%0], [%1], 8;" :: "r"(dst), "l"(src));
}
__device__ __forceinline__ void cpa16(uint32_t dst, const void* src) {
    asm volatile("cp.async.cg.shared.global [%0], [%1], 16;" :: "r"(dst), "l"(src));
}
__device__ __forceinline__ void cpa_commit() {
    asm volatile("cp.async.commit_group;" ::: "memory");
}
__device__ __forceinline__ void cpa_wait1() {
    asm volatile("cp.async.wait_group 1;" ::: "memory");
}
__device__ __forceinline__ void cpa_wait0() {
    asm volatile("cp.async.wait_group 0;" ::: "memory");
}

// ---------------- smem layout ----------------
constexpr int STAGES = 3;
constexpr int KC = 64;          // k per chunk
constexpr int KPC = KC / 2;     // 32 k-pairs
constexpr int NCH = 512 / KC;   // 8 chunks
constexpr int NTHREADS = 512;   // 16 warps
__device__ __forceinline__ int a_off(int st, int kp, int row) {
    return st * (KPC * 128) + kp * 128 + (row ^ ((kp & 3) << 2));
}
__device__ __forceinline__ int b_off(int st, int kp, int col) {
    return STAGES * (KPC * 128) + st * (KPC * 128) + kp * 128 + (col ^ ((kp & 3) << 2));
}
constexpr int SMEM_BYTES = 2 * STAGES * KPC * 128 * 8;  // 192 KB

// fragment set for one k16 s-block, 32x32 warp tile
struct Frags {
    uint32_t ah[2][4], aml[2][4];
    uint32_t bh[4][2], bml[4][2];
};

// ======================= async bf16-split GEMM body =======================
// C[bm:bm+128, bn:bn+128] for C = A[M,512] @ B[512,Ncol] + bias
// 512 threads, 16 warps in 4(m) x 4(n) grid, 32x32 warp tile.
// MODE 0: A from pre-split global Asp [kp][AS rows], row offset abase (cp.async)
// MODE 1: A row m = sum of 4 child h-rows (fp32 H) of node pbase+m (reg gather)
template <int MODE>
__device__ __forceinline__
void gemm_body(const uint2* __restrict__ Asp, int AS, int abase,
               const float* __restrict__ H, int pbase,
               const uint2* __restrict__ Bsp,
               const float* __restrict__ bias, float* __restrict__ C,
               int M, int Ncol, int bm, int bn) {
    extern __shared__ uint2 sm2[];
    const uint32_t sbase = (uint32_t)__cvta_generic_to_shared(sm2);
    const int tid = threadIdx.x;
    const int wid = tid >> 5;
    const int lid = tid & 31;
    const int wm = (wid & 3) * 32;       // 4 m-tiles of 32
    const int wn = (wid >> 2) * 32;      // 4 n-tiles of 32
    const int g = lid >> 2;
    const int c3 = lid & 3;

    // staging assignments (512 threads)
    const int srow = tid & 127;          // A row
    const int skpb = (tid >> 7) * 8;     // A: 8 kp per thread (4 groups x 8 = 32 kp)
    const int scol = (tid & 63) * 2;     // B: col pair
    const int skp4 = (tid >> 6) * 4;     // B: 4 kp per thread (8 groups x 4 = 32 kp)

    auto issueStage = [&](int ch, int st) {
        if (MODE == 0) {
#pragma unroll
            for (int i = 0; i < 8; ++i) {
                int kp = skpb + i;
                const uint2* src = Asp + (size_t)(ch * KPC + kp) * AS + abase + bm + srow;
                cpa8(sbase + (uint32_t)a_off(st, kp, srow) * 8, src);
            }
        } else {
            int gr = bm + srow;
            float v[16];
#pragma unroll
            for (int j = 0; j < 16; ++j) v[j] = 0.f;
            if (gr < M) {
                int p = pbase + gr;
                int kb = ch * KC + skpb * 2;
#pragma unroll
                for (int kk = 0; kk < 4; ++kk) {
                    int cid = child_id(p, kk);
                    const float* hp = H + (size_t)cid * 512 + kb;
#pragma unroll
                    for (int j = 0; j < 4; ++j) {
                        float4 t = *reinterpret_cast<const float4*>(hp + 4 * j);
                        v[4 * j + 0] += t.x; v[4 * j + 1] += t.y;
                        v[4 * j + 2] += t.z; v[4 * j + 3] += t.w;
                    }
                }
            }
#pragma unroll
            for (int i = 0; i < 8; ++i)
                sm2[a_off(st, skpb + i, srow)] = split_pack(v[2 * i], v[2 * i + 1]);
        }
#pragma unroll
        for (int i = 0; i < 4; ++i) {
            int kp = skp4 + i;
            const uint2* src = Bsp + (size_t)(ch * KPC + kp) * Ncol + bn + scol;
            cpa16(sbase + (uint32_t)b_off(st, kp, scol) * 8, src);
        }
    };

    float acc[2][4][4];
#pragma unroll
    for (int mt = 0; mt < 2; ++mt)
#pragma unroll
        for (int nt = 0; nt < 4; ++nt)
#pragma unroll
            for (int i = 0; i < 4; ++i) acc[mt][nt][i] = 0.f;

    auto loadFrag = [&](Frags& F, int st, int s) {
#pragma unroll
        for (int mt = 0; mt < 2; ++mt) {
            int r0 = wm + mt * 16 + g;
            uint2 t;
            t = sm2[a_off(st, s * 8 + c3, r0)];          F.ah[mt][0] = t.x; F.aml[mt][0] = t.y;
            t = sm2[a_off(st, s * 8 + c3, r0 + 8)];      F.ah[mt][1] = t.x; F.aml[mt][1] = t.y;
            t = sm2[a_off(st, s * 8 + c3 + 4, r0)];      F.ah[mt][2] = t.x; F.aml[mt][2] = t.y;
            t = sm2[a_off(st, s * 8 + c3 + 4, r0 + 8)];  F.ah[mt][3] = t.x; F.aml[mt][3] = t.y;
        }
#pragma unroll
        for (int nt = 0; nt < 4; ++nt) {
            int n0 = wn + nt * 8 + g;
            uint2 t;
            t = sm2[b_off(st, s * 8 + c3, n0)];      F.bh[nt][0] = t.x; F.bml[nt][0] = t.y;
            t = sm2[b_off(st, s * 8 + c3 + 4, n0)];  F.bh[nt][1] = t.x; F.bml[nt][1] = t.y;
        }
    };

    auto runMMA = [&](const Frags& F) {
#pragma unroll
        for (int mt = 0; mt < 2; ++mt)
#pragma unroll
            for (int nt = 0; nt < 4; ++nt)
                mma16(acc[mt][nt], F.ah[mt], F.bh[nt]);
#pragma unroll
        for (int mt = 0; mt < 2; ++mt)
#pragma unroll
            for (int nt = 0; nt < 4; ++nt)
                mma16(acc[mt][nt], F.ah[mt], F.bml[nt]);
#pragma unroll
        for (int mt = 0; mt < 2; ++mt)
#pragma unroll
            for (int nt = 0; nt < 4; ++nt)
                mma16(acc[mt][nt], F.aml[mt], F.bh[nt]);
    };

    // prologue: stages 0..STAGES-2 in flight
#pragma unroll
    for (int s = 0; s < STAGES - 1; ++s) {
        issueStage(s, s);
        cpa_commit();
    }

    Frags F;
    for (int ch = 0; ch < NCH; ++ch) {
        if (ch + STAGES - 1 < NCH) cpa_wait1(); else cpa_wait0();
        __syncthreads();
        int nx = ch + STAGES - 1;
        if (nx < NCH) {
            issueStage(nx, nx % STAGES);
            cpa_commit();
        }
        const int st = ch % STAGES;
#pragma unroll
        for (int s = 0; s < 4; ++s) {
            loadFrag(F, st, s);
            runMMA(F);
        }
    }

    // epilogue
#pragma unroll
    for (int mt = 0; mt < 2; ++mt) {
        int r = bm + wm + mt * 16 + g;
        int r2 = r + 8;
#pragma unroll
        for (int nt = 0; nt < 4; ++nt) {
            int col = bn + wn + nt * 8 + 2 * c3;
            float b0 = bias[col], b1 = bias[col + 1];
            if (r < M) {
                float2 o = make_float2(acc[mt][nt][0] + b0, acc[mt][nt][1] + b1);
                *reinterpret_cast<float2*>(&C[(size_t)r * Ncol + col]) = o;
            }
            if (r2 < M) {
                float2 o = make_float2(acc[mt][nt][2] + b0, acc[mt][nt][3] + b1);
                *reinterpret_cast<float2*>(&C[(size_t)r2 * Ncol + col]) = o;
            }
        }
    }
}

// plain single-GEMM kernel (used for ifou)
template <int MODE>
__global__ __launch_bounds__(NTHREADS, 1)
void gemm_async(const uint2* __restrict__ Asp, int AS, int abase,
                const float* __restrict__ H, int pbase,
                const uint2* __restrict__ Bsp,
                const float* __restrict__ bias, float* __restrict__ C,
                int M, int Ncol) {
    gemm_body<MODE>(Asp, AS, abase, H, pbase, Bsp, bias, C, M, Ncol,
                    blockIdx.y * 128, blockIdx.x * 128);
}

// dual kernel: z=0 -> iou GEMM (MODE1 gather), z=1 -> fw GEMM (MODE0 dense)
__global__ __launch_bounds__(NTHREADS, 1)
void gemm_dual(const float* __restrict__ H, int pbase,
               const uint2* __restrict__ wss, const float* __restrict__ bs,
               float* __restrict__ iou, int M1,
               const uint2* __restrict__ hsp, int abase,
               const uint2* __restrict__ wfs, const float* __restrict__ bf,
               float* __restrict__ fwout, int M0) {
    if (blockIdx.z == 0) {
        if ((int)blockIdx.x >= 12 || (int)(blockIdx.y * 128) >= M1) return;
        gemm_body<1>(nullptr, 0, 0, H, pbase, wss, bs, iou, M1, 1536,
                     blockIdx.y * 128, blockIdx.x * 128);
    } else {
        if ((int)blockIdx.x >= 4 || (int)(blockIdx.y * 128) >= M0) return;
        gemm_body<0>(hsp, HS, abase, nullptr, 0, wfs, bf, fwout, M0, 512,
                     blockIdx.y * 128, blockIdx.x * 128);
    }
}

// ---------------- pre-split kernels ----------------
// all three weight matrices in one launch, flattened over 4096 columns
__global__ void split_w_all(const float* __restrict__ Wx, const float* __restrict__ Ws,
                            const float* __restrict__ Wf,
                            uint2* __restrict__ wxs, uint2* __restrict__ wss,
                            uint2* __restrict__ wfs) {
    int n = blockIdx.x * 256 + threadIdx.x;   // 0..4095
    int kp = blockIdx.y;                      // 0..255
    const float* W; uint2* out; int Ncol; int nn;
    if (n < 2048)      { W = Wx; out = wxs; Ncol = 2048; nn = n; }
    else if (n < 3584) { W = Ws; out = wss; Ncol = 1536; nn = n - 2048; }
    else               { W = Wf; out = wfs; Ncol = 512;  nn = n - 3584; }
    float a = W[(size_t)(2 * kp) * Ncol + nn];
    float b = W[(size_t)(2 * kp + 1) * Ncol + nn];
    out[(size_t)kp * Ncol + nn] = split_pack(a, b);
}

// inputs[4096][512] -> isp[kp][4096] (smem transpose)
__global__ void split_in_kernel(const float* __restrict__ in, uint2* __restrict__ out) {
    __shared__ float2 tile[32][33];
    int row = blockIdx.x * 32 + threadIdx.y;
    int kp = blockIdx.y * 32 + threadIdx.x;
    tile[threadIdx.y][threadIdx.x] = *reinterpret_cast<const float2*>(in + (size_t)row * 512 + 2 * kp);
    __syncthreads();
    int orow = blockIdx.x * 32 + threadIdx.x;
    int okp = blockIdx.y * 32 + threadIdx.y;
    float2 v = tile[threadIdx.x][threadIdx.y];
    out[(size_t)okp * 4096 + orow] = split_pack(v.x, v.y);
}

// ---------------- elementwise kernels ----------------
__global__ void init_kernel(float* cbuf, float* hbuf) {
    int j = threadIdx.x;
    cbuf[(size_t)NN * MEM + j] = 0.f;
    hbuf[(size_t)NN * MEM + j] = 0.f;
}

__global__ void leaf_kernel(const float* __restrict__ ifou, const float* __restrict__ bs,
                            float* __restrict__ cbuf, float* __restrict__ hbuf,
                            uint2* __restrict__ hsp) {
    int p = blockIdx.x;
    int j = threadIdx.x;
    const float* r = ifou + (size_t)p * 2048;
    float iv = sigmoidf_(r[j] + bs[j]);
    float ov = sigmoidf_(r[1024 + j] + bs[512 + j]);
    float uv = tanhf(r[1536 + j] + bs[1024 + j]);
    float c = iv * uv;
    float h = ov * tanhf(c);
    cbuf[(size_t)p * MEM + j] = c;
    hbuf[(size_t)p * MEM + j] = h;
    float hn = __shfl_down_sync(0xffffffffu, h, 1);
    if ((j & 1) == 0) hsp[(size_t)(j >> 1) * HS + p] = split_pack(h, hn);
}

__global__ void combine_kernel(const float* __restrict__ ifou, const float* __restrict__ iou,
                               const float* __restrict__ fw, float* __restrict__ cbuf,
                               float* __restrict__ hbuf, uint2* __restrict__ hsp, int base) {
    int m = blockIdx.x;
    int j = threadIdx.x;
    int p = base + m;
    const float* r = ifou + (size_t)p * 2048;
    float ix = r[j], fx = r[512 + j], ox = r[1024 + j], ux = r[1536 + j];
    float iv = sigmoidf_(ix + iou[(size_t)m * 1536 + j]);
    float ov = sigmoidf_(ox + iou[(size_t)m * 1536 + 512 + j]);
    float uv = tanhf(ux + iou[(size_t)m * 1536 + 1024 + j]);
    float c = iv * uv;
#pragma unroll
    for (int k = 0; k < 4; ++k) {
        int cid = child_id(p, k);
        float f = sigmoidf_(fw[(size_t)cid * MEM + j] + fx);
        c += f * cbuf[(size_t)cid * MEM + j];
    }
    float h = ov * tanhf(c);
    cbuf[(size_t)p * MEM + j] = c;
    hbuf[(size_t)p * MEM + j] = h;
    float hn = __shfl_down_sync(0xffffffffu, h, 1);
    if ((j & 1) == 0) hsp[(size_t)(j >> 1) * HS + p] = split_pack(h, hn);
}

__global__ void copyout_kernel(const float* __restrict__ hbuf, float* __restrict__ out) {
    out[threadIdx.x] = hbuf[(size_t)(NN - 1) * MEM + threadIdx.x];
}

// ---------------- launch ----------------
extern "C" void kernel_launch(void* const* d_in, const int* in_sizes, int n_in,
                              void* d_out, int out_size) {
    const float* inputs = (const float*)d_in[0];
    const float* Wx     = (const float*)d_in[1];
    const float* bx     = (const float*)d_in[2];
    const float* Ws     = (const float*)d_in[3];
    const float* bs     = (const float*)d_in[4];
    const float* Wf     = (const float*)d_in[5];
    const float* bf     = (const float*)d_in[6];
    float* out = (float*)d_out;

    float *ifou, *cbuf, *hbuf, *iou, *fw;
    uint2 *wxs, *wss, *wfs, *isp, *hsp;
    cudaGetSymbolAddress((void**)&ifou, g_ifou);
    cudaGetSymbolAddress((void**)&cbuf, g_c);
    cudaGetSymbolAddress((void**)&hbuf, g_h);
    cudaGetSymbolAddress((void**)&iou, g_iou);
    cudaGetSymbolAddress((void**)&fw, g_fw);
    cudaGetSymbolAddress((void**)&wxs, g_wxs);
    cudaGetSymbolAddress((void**)&wss, g_wss);
    cudaGetSymbolAddress((void**)&wfs, g_wfs);
    cudaGetSymbolAddress((void**)&isp, g_isp);
    cudaGetSymbolAddress((void**)&hsp, g_hsp);

    cudaFuncSetAttribute(gemm_async<0>, cudaFuncAttributeMaxDynamicSharedMemorySize, SMEM_BYTES);
    cudaFuncSetAttribute(gemm_dual, cudaFuncAttributeMaxDynamicSharedMemorySize, SMEM_BYTES);

    init_kernel<<<1, 512>>>(cbuf, hbuf);

    // pre-split constants
    split_w_all<<<dim3(16, 256), 256>>>(Wx, Ws, Wf, wxs, wss, wfs);
    split_in_kernel<<<dim3(4096 / 32, 256 / 32), dim3(32, 32)>>>(inputs, isp);

    // ifou = inputs @ Wx + bx
    gemm_async<0><<<dim3(2048 / 128, 4096 / 128), NTHREADS, SMEM_BYTES>>>(
        isp, 4096, 0, nullptr, 0, wxs, bx, ifou, NN, 2048);

    leaf_kernel<<<3072, 512>>>(ifou, bs, cbuf, hbuf, hsp);

    static const int baseArr[6] = {3072, 3755, 4011, 4075, 4091, 4095};
    static const int cntArr[6]  = {683, 256, 64, 16, 4, 1};
    int prevBase = 0, prevCnt = 3072;
    for (int l = 0; l < 6; ++l) {
        int m = cntArr[l], base = baseArr[l];
        int gy = (m + 127) / 128;
        int gy0 = (prevCnt + 127) / 128;
        int gymax = gy > gy0 ? gy : gy0;
        // z=0: iou_l = (sum child h) @ Ws + bs ; z=1: fw of previous level
        gemm_dual<<<dim3(12, gymax, 2), NTHREADS, SMEM_BYTES>>>(
            hbuf, base, wss, bs, iou, m,
            hsp, prevBase, wfs, bf, fw + (size_t)prevBase * 512, prevCnt);
        combine_kernel<<<m, 512>>>(ifou, iou, fw, cbuf, hbuf, hsp, base);
        prevBase = base;
        prevCnt = m;
    }

    copyout_kernel<<<1, 512>>>(hbuf, out);
}

// round 13
// speedup vs baseline: 1.8557x; 1.4928x over previous
#include <cuda_runtime.h>
#include <cuda_bf16.h>
#include <math.h>
#include <stdint.h>

#define NN 4096
#define MEM 512
#define HS 4224   // padded row count for h_split (level tiles read past last node)

constexpr int NSPLIT = 4;                     // split-K factor for level GEMMs
constexpr size_t IOU_P = (size_t)683 * 1536;  // iou partial slice stride
constexpr size_t FW_P  = (size_t)(NN + 1) * MEM;  // fw partial slice stride

// ---------------- scratch (static device globals; no allocation) ----------------
__device__ float g_ifou[NN * 2048];
__device__ float g_c[(NN + 1) * MEM];
__device__ float g_h[(NN + 1) * MEM];
__device__ float g_iou[NSPLIT * 683 * 1536];        // split-K partials
__device__ float g_fw[NSPLIT * (NN + 1) * MEM];     // split-K partials (sentinel rows stay 0)
// pre-split (hi,mid) bf16x2 pairs, packed per k-pair
__device__ uint2 g_wxs[256 * 2048];   // Wx split [kp][n]
__device__ uint2 g_wss[256 * 1536];   // Ws split [kp][n]
__device__ uint2 g_wfs[256 * 512];    // Wf split [kp][n]
__device__ uint2 g_isp[256 * 4096];   // inputs split, transposed [kp][row]
__device__ uint2 g_hsp[256 * HS];     // h split, transposed [kp][node]

__device__ __forceinline__ float sigmoidf_(float x) { return 1.0f / (1.0f + expf(-x)); }

__device__ __forceinline__ int child_id(int p, int k) {
    int c = 4 * p - 12289 + k;
    return c < 0 ? NN : c;
}

// ---------------- bf16 split helpers ----------------
__device__ __forceinline__ uint2 split_pack(float x0, float x1) {
    __nv_bfloat162 h = __floats2bfloat162_rn(x0, x1);
    float r0 = x0 - __bfloat162float(h.x);
    float r1 = x1 - __bfloat162float(h.y);
    __nv_bfloat162 m = __floats2bfloat162_rn(r0, r1);
    uint2 o;
    o.x = *reinterpret_cast<uint32_t*>(&h);
    o.y = *reinterpret_cast<uint32_t*>(&m);
    return o;
}

__device__ __forceinline__ void mma16(float* d, const uint32_t* a, const uint32_t* b) {
    asm volatile(
        "mma.sync.aligned.m16n8k16.row.col.f32.bf16.bf16.f32 "
        "{%0,%1,%2,%3}, {%4,%5,%6,%7}, {%8,%9}, {%0,%1,%2,%3};"
        : "+f"(d[0]), "+f"(d[1]), "+f"(d[2]), "+f"(d[3])
        : "r"(a[0]), "r"(a[1]), "r"(a[2]), "r"(a[3]), "r"(b[0]), "r"(b[1]));
}

__device__ __forceinline__ void cpa8(uint32_t dst, const void* src) {
    asm volatile("cp.async.ca.shared.global [%0], [%1], 8;" :: "r"(dst), "l"(src));
}
__device__ __forceinline__ void cpa16(uint32_t dst, const void* src) {
    asm volatile("cp.async.cg.shared.global [%0], [%1], 16;" :: "r"(dst), "l"(src));
}
__device__ __forceinline__ void cpa_commit() {
    asm volatile("cp.async.commit_group;" ::: "memory");
}
__device__ __forceinline__ void cpa_wait1() {
    asm volatile("cp.async.wait_group 1;" ::: "memory");
}
__device__ __forceinline__ void cpa_wait0() {
    asm volatile("cp.async.wait_group 0;" ::: "memory");
}

// ---------------- smem layout ----------------
constexpr int STAGES = 3;
constexpr int KC = 64;          // k per chunk
constexpr int KPC = KC / 2;     // 32 k-pairs
constexpr int NCH = 512 / KC;   // 8 chunks total
constexpr int NTHREADS = 512;   // 16 warps
__device__ __forceinline__ int a_off(int st, int kp, int row) {
    return st * (KPC * 128) + kp * 128 + (row ^ ((kp & 3) << 2));
}
__device__ __forceinline__ int b_off(int st, int kp, int col) {
    return STAGES * (KPC * 128) + st * (KPC * 128) + kp * 128 + (col ^ ((kp & 3) << 2));
}
constexpr int SMEM_BYTES = 2 * STAGES * KPC * 128 * 8;  // 192 KB

// fragment set for one k16 s-block, 32x32 warp tile
struct Frags {
    uint32_t ah[2][4], aml[2][4];
    uint32_t bh[4][2], bml[4][2];
};

// ======================= async bf16-split GEMM body =======================
// Computes C[bm:bm+128, bn:bn+128] partial over K chunks [ch0, ch0+nch)
// of C = A[M,512] @ B[512,Ncol] (+ bias if non-null).
// 512 threads, 16 warps in 4(m) x 4(n) grid, 32x32 warp tile.
// MODE 0: A from pre-split global Asp [kp][AS rows], row offset abase (cp.async)
// MODE 1: A row m = sum of 4 child h-rows (fp32 H) of node pbase+m (reg gather)
template <int MODE>
__device__ __forceinline__
void gemm_body(const uint2* __restrict__ Asp, int AS, int abase,
               const float* __restrict__ H, int pbase,
               const uint2* __restrict__ Bsp,
               const float* __restrict__ bias, float* __restrict__ C,
               int M, int Ncol, int bm, int bn, int ch0, int nch) {
    extern __shared__ uint2 sm2[];
    const uint32_t sbase = (uint32_t)__cvta_generic_to_shared(sm2);
    const int tid = threadIdx.x;
    const int wid = tid >> 5;
    const int lid = tid & 31;
    const int wm = (wid & 3) * 32;       // 4 m-tiles of 32
    const int wn = (wid >> 2) * 32;      // 4 n-tiles of 32
    const int g = lid >> 2;
    const int c3 = lid & 3;

    // staging assignments (512 threads)
    const int srow = tid & 127;          // A row
    const int skpb = (tid >> 7) * 8;     // A: 8 kp per thread (4 groups x 8 = 32 kp)
    const int scol = (tid & 63) * 2;     // B: col pair
    const int skp4 = (tid >> 6) * 4;     // B: 4 kp per thread (8 groups x 4 = 32 kp)

    auto issueStage = [&](int chg, int st) {   // chg = GLOBAL chunk index
        if (MODE == 0) {
#pragma unroll
            for (int i = 0; i < 8; ++i) {
                int kp = skpb + i;
                const uint2* src = Asp + (size_t)(chg * KPC + kp) * AS + abase + bm + srow;
                cpa8(sbase + (uint32_t)a_off(st, kp, srow) * 8, src);
            }
        } else {
            int gr = bm + srow;
            float v[16];
#pragma unroll
            for (int j = 0; j < 16; ++j) v[j] = 0.f;
            if (gr < M) {
                int p = pbase + gr;
                int kb = chg * KC + skpb * 2;
#pragma unroll
                for (int kk = 0; kk < 4; ++kk) {
                    int cid = child_id(p, kk);
                    const float* hp = H + (size_t)cid * 512 + kb;
#pragma unroll
                    for (int j = 0; j < 4; ++j) {
                        float4 t = *reinterpret_cast<const float4*>(hp + 4 * j);
                        v[4 * j + 0] += t.x; v[4 * j + 1] += t.y;
                        v[4 * j + 2] += t.z; v[4 * j + 3] += t.w;
                    }
                }
            }
#pragma unroll
            for (int i = 0; i < 8; ++i)
                sm2[a_off(st, skpb + i, srow)] = split_pack(v[2 * i], v[2 * i + 1]);
        }
#pragma unroll
        for (int i = 0; i < 4; ++i) {
            int kp = skp4 + i;
            const uint2* src = Bsp + (size_t)(chg * KPC + kp) * Ncol + bn + scol;
            cpa16(sbase + (uint32_t)b_off(st, kp, scol) * 8, src);
        }
    };

    float acc[2][4][4];
#pragma unroll
    for (int mt = 0; mt < 2; ++mt)
#pragma unroll
        for (int nt = 0; nt < 4; ++nt)
#pragma unroll
            for (int i = 0; i < 4; ++i) acc[mt][nt][i] = 0.f;

    auto loadFrag = [&](Frags& F, int st, int s) {
#pragma unroll
        for (int mt = 0; mt < 2; ++mt) {
            int r0 = wm + mt * 16 + g;
            uint2 t;
            t = sm2[a_off(st, s * 8 + c3, r0)];          F.ah[mt][0] = t.x; F.aml[mt][0] = t.y;
            t = sm2[a_off(st, s * 8 + c3, r0 + 8)];      F.ah[mt][1] = t.x; F.aml[mt][1] = t.y;
            t = sm2[a_off(st, s * 8 + c3 + 4, r0)];      F.ah[mt][2] = t.x; F.aml[mt][2] = t.y;
            t = sm2[a_off(st, s * 8 + c3 + 4, r0 + 8)];  F.ah[mt][3] = t.x; F.aml[mt][3] = t.y;
        }
#pragma unroll
        for (int nt = 0; nt < 4; ++nt) {
            int n0 = wn + nt * 8 + g;
            uint2 t;
            t = sm2[b_off(st, s * 8 + c3, n0)];      F.bh[nt][0] = t.x; F.bml[nt][0] = t.y;
            t = sm2[b_off(st, s * 8 + c3 + 4, n0)];  F.bh[nt][1] = t.x; F.bml[nt][1] = t.y;
        }
    };

    auto runMMA = [&](const Frags& F) {
#pragma unroll
        for (int mt = 0; mt < 2; ++mt)
#pragma unroll
            for (int nt = 0; nt < 4; ++nt)
                mma16(acc[mt][nt], F.ah[mt], F.bh[nt]);
#pragma unroll
        for (int mt = 0; mt < 2; ++mt)
#pragma unroll
            for (int nt = 0; nt < 4; ++nt)
                mma16(acc[mt][nt], F.ah[mt], F.bml[nt]);
#pragma unroll
        for (int mt = 0; mt < 2; ++mt)
#pragma unroll
            for (int nt = 0; nt < 4; ++nt)
                mma16(acc[mt][nt], F.aml[mt], F.bh[nt]);
    };

    // prologue: fill up to STAGES-1 stages (bounded by nch)
    const int pro = (nch < STAGES - 1) ? nch : (STAGES - 1);
    for (int s = 0; s < pro; ++s) {
        issueStage(ch0 + s, s);
        cpa_commit();
    }

    Frags F;
    for (int chl = 0; chl < nch; ++chl) {
        int issued = chl + STAGES - 1;
        if (issued > nch) issued = nch;
        if (issued - chl - 1 >= 1) cpa_wait1(); else cpa_wait0();
        __syncthreads();
        int nx = chl + STAGES - 1;
        if (nx < nch) {
            issueStage(ch0 + nx, nx % STAGES);
            cpa_commit();
        }
        const int st = chl % STAGES;
#pragma unroll
        for (int s = 0; s < 4; ++s) {
            loadFrag(F, st, s);
            runMMA(F);
        }
    }

    // epilogue
#pragma unroll
    for (int mt = 0; mt < 2; ++mt) {
        int r = bm + wm + mt * 16 + g;
        int r2 = r + 8;
#pragma unroll
        for (int nt = 0; nt < 4; ++nt) {
            int col = bn + wn + nt * 8 + 2 * c3;
            float b0 = bias ? bias[col] : 0.f;
            float b1 = bias ? bias[col + 1] : 0.f;
            if (r < M) {
                float2 o = make_float2(acc[mt][nt][0] + b0, acc[mt][nt][1] + b1);
                *reinterpret_cast<float2*>(&C[(size_t)r * Ncol + col]) = o;
            }
            if (r2 < M) {
                float2 o = make_float2(acc[mt][nt][2] + b0, acc[mt][nt][3] + b1);
                *reinterpret_cast<float2*>(&C[(size_t)r2 * Ncol + col]) = o;
            }
        }
    }
}

// plain single-GEMM kernel (used for ifou; full K)
template <int MODE>
__global__ __launch_bounds__(NTHREADS, 1)
void gemm_async(const uint2* __restrict__ Asp, int AS, int abase,
                const float* __restrict__ H, int pbase,
                const uint2* __restrict__ Bsp,
                const float* __restrict__ bias, float* __restrict__ C,
                int M, int Ncol) {
    gemm_body<MODE>(Asp, AS, abase, H, pbase, Bsp, bias, C, M, Ncol,
                    blockIdx.y * 128, blockIdx.x * 128, 0, NCH);
}

// dual split-K kernel: z = split + 4*sel
//   sel 0 -> iou GEMM (MODE1 gather), sel 1 -> fw GEMM (MODE0 dense)
// each split handles 2 of the 8 K-chunks; bias folded into split 0.
__global__ __launch_bounds__(NTHREADS, 1)
void gemm_dual(const float* __restrict__ H, int pbase,
               const uint2* __restrict__ wss, const float* __restrict__ bs,
               float* __restrict__ ioup, int M1,
               const uint2* __restrict__ hsp, int abase,
               const uint2* __restrict__ wfs, const float* __restrict__ bf,
               float* __restrict__ fwp, int M0) {
    const int split = blockIdx.z & 3;
    const int ch0 = split * (NCH / NSPLIT);
    if (blockIdx.z < 4) {
        if ((int)blockIdx.x >= 12 || (int)(blockIdx.y * 128) >= M1) return;
        gemm_body<1>(nullptr, 0, 0, H, pbase, wss,
                     split == 0 ? bs : nullptr,
                     ioup + (size_t)split * IOU_P, M1, 1536,
                     blockIdx.y * 128, blockIdx.x * 128, ch0, NCH / NSPLIT);
    } else {
        if ((int)blockIdx.x >= 4 || (int)(blockIdx.y * 128) >= M0) return;
        gemm_body<0>(hsp, HS, abase, nullptr, 0, wfs,
                     split == 0 ? bf : nullptr,
                     fwp + (size_t)split * FW_P, M0, 512,
                     blockIdx.y * 128, blockIdx.x * 128, ch0, NCH / NSPLIT);
    }
}

// ---------------- pre-split kernels ----------------
__global__ void split_w_all(const float* __restrict__ Wx, const float* __restrict__ Ws,
                            const float* __restrict__ Wf,
                            uint2* __restrict__ wxs, uint2* __restrict__ wss,
                            uint2* __restrict__ wfs) {
    int n = blockIdx.x * 256 + threadIdx.x;   // 0..4095
    int kp = blockIdx.y;                      // 0..255
    const float* W; uint2* out; int Ncol; int nn;
    if (n < 2048)      { W = Wx; out = wxs; Ncol = 2048; nn = n; }
    else if (n < 3584) { W = Ws; out = wss; Ncol = 1536; nn = n - 2048; }
    else               { W = Wf; out = wfs; Ncol = 512;  nn = n - 3584; }
    float a = W[(size_t)(2 * kp) * Ncol + nn];
    float b = W[(size_t)(2 * kp + 1) * Ncol + nn];
    out[(size_t)kp * Ncol + nn] = split_pack(a, b);
}

// inputs[4096][512] -> isp[kp][4096] (smem transpose)
__global__ void split_in_kernel(const float* __restrict__ in, uint2* __restrict__ out) {
    __shared__ float2 tile[32][33];
    int row = blockIdx.x * 32 + threadIdx.y;
    int kp = blockIdx.y * 32 + threadIdx.x;
    tile[threadIdx.y][threadIdx.x] = *reinterpret_cast<const float2*>(in + (size_t)row * 512 + 2 * kp);
    __syncthreads();
    int orow = blockIdx.x * 32 + threadIdx.x;
    int okp = blockIdx.y * 32 + threadIdx.y;
    float2 v = tile[threadIdx.x][threadIdx.y];
    out[(size_t)okp * 4096 + orow] = split_pack(v.x, v.y);
}

// ---------------- elementwise kernels ----------------
__global__ void init_kernel(float* cbuf, float* hbuf) {
    int j = threadIdx.x;
    cbuf[(size_t)NN * MEM + j] = 0.f;
    hbuf[(size_t)NN * MEM + j] = 0.f;
}

__global__ void leaf_kernel(const float* __restrict__ ifou, const float* __restrict__ bs,
                            float* __restrict__ cbuf, float* __restrict__ hbuf,
                            uint2* __restrict__ hsp) {
    int p = blockIdx.x;
    int j = threadIdx.x;
    const float* r = ifou + (size_t)p * 2048;
    float iv = sigmoidf_(r[j] + bs[j]);
    float ov = sigmoidf_(r[1024 + j] + bs[512 + j]);
    float uv = tanhf(r[1536 + j] + bs[1024 + j]);
    float c = iv * uv;
    float h = ov * tanhf(c);
    cbuf[(size_t)p * MEM + j] = c;
    hbuf[(size_t)p * MEM + j] = h;
    float hn = __shfl_down_sync(0xffffffffu, h, 1);
    if ((j & 1) == 0) hsp[(size_t)(j >> 1) * HS + p] = split_pack(h, hn);
}

// combine: sums the 4 split-K partials of iou and fw (fixed order, deterministic)
__global__ void combine_kernel(const float* __restrict__ ifou, const float* __restrict__ ioup,
                               const float* __restrict__ fwp, float* __restrict__ cbuf,
                               float* __restrict__ hbuf, uint2* __restrict__ hsp, int base) {
    int m = blockIdx.x;
    int j = threadIdx.x;
    int p = base + m;
    const float* r = ifou + (size_t)p * 2048;
    float ix = r[j], fx = r[512 + j], ox = r[1024 + j], ux = r[1536 + j];
    size_t o = (size_t)m * 1536 + j;
    float i_s = ioup[o] + ioup[IOU_P + o] + ioup[2 * IOU_P + o] + ioup[3 * IOU_P + o];
    float o_s = ioup[o + 512] + ioup[IOU_P + o + 512] + ioup[2 * IOU_P + o + 512] + ioup[3 * IOU_P + o + 512];
    float u_s = ioup[o + 1024] + ioup[IOU_P + o + 1024] + ioup[2 * IOU_P + o + 1024] + ioup[3 * IOU_P + o + 1024];
    float iv = sigmoidf_(ix + i_s);
    float ov = sigmoidf_(ox + o_s);
    float uv = tanhf(ux + u_s);
    float c = iv * uv;
#pragma unroll
    for (int k = 0; k < 4; ++k) {
        int cid = child_id(p, k);
        size_t fo = (size_t)cid * MEM + j;
        float fraw = fwp[fo] + fwp[FW_P + fo] + fwp[2 * FW_P + fo] + fwp[3 * FW_P + fo];
        float f = sigmoidf_(fraw + fx);
        c += f * cbuf[(size_t)cid * MEM + j];
    }
    float h = ov * tanhf(c);
    cbuf[(size_t)p * MEM + j] = c;
    hbuf[(size_t)p * MEM + j] = h;
    float hn = __shfl_down_sync(0xffffffffu, h, 1);
    if ((j & 1) == 0) hsp[(size_t)(j >> 1) * HS + p] = split_pack(h, hn);
}

__global__ void copyout_kernel(const float* __restrict__ hbuf, float* __restrict__ out) {
    out[threadIdx.x] = hbuf[(size_t)(NN - 1) * MEM + threadIdx.x];
}

// ---------------- launch ----------------
extern "C" void kernel_launch(void* const* d_in, const int* in_sizes, int n_in,
                              void* d_out, int out_size) {
    const float* inputs = (const float*)d_in[0];
    const float* Wx     = (const float*)d_in[1];
    const float* bx     = (const float*)d_in[2];
    const float* Ws     = (const float*)d_in[3];
    const float* bs     = (const float*)d_in[4];
    const float* Wf     = (const float*)d_in[5];
    const float* bf     = (const float*)d_in[6];
    float* out = (float*)d_out;

    float *ifou, *cbuf, *hbuf, *iou, *fw;
    uint2 *wxs, *wss, *wfs, *isp, *hsp;
    cudaGetSymbolAddress((void**)&ifou, g_ifou);
    cudaGetSymbolAddress((void**)&cbuf, g_c);
    cudaGetSymbolAddress((void**)&hbuf, g_h);
    cudaGetSymbolAddress((void**)&iou, g_iou);
    cudaGetSymbolAddress((void**)&fw, g_fw);
    cudaGetSymbolAddress((void**)&wxs, g_wxs);
    cudaGetSymbolAddress((void**)&wss, g_wss);
    cudaGetSymbolAddress((void**)&wfs, g_wfs);
    cudaGetSymbolAddress((void**)&isp, g_isp);
    cudaGetSymbolAddress((void**)&hsp, g_hsp);

    cudaFuncSetAttribute(gemm_async<0>, cudaFuncAttributeMaxDynamicSharedMemorySize, SMEM_BYTES);
    cudaFuncSetAttribute(gemm_dual, cudaFuncAttributeMaxDynamicSharedMemorySize, SMEM_BYTES);

    init_kernel<<<1, 512>>>(cbuf, hbuf);

    // pre-split constants
    split_w_all<<<dim3(16, 256), 256>>>(Wx, Ws, Wf, wxs, wss, wfs);
    split_in_kernel<<<dim3(4096 / 32, 256 / 32), dim3(32, 32)>>>(inputs, isp);

    // ifou = inputs @ Wx + bx  (full-K, throughput-bound)
    gemm_async<0><<<dim3(2048 / 128, 4096 / 128), NTHREADS, SMEM_BYTES>>>(
        isp, 4096, 0, nullptr, 0, wxs, bx, ifou, NN, 2048);

    leaf_kernel<<<3072, 512>>>(ifou, bs, cbuf, hbuf, hsp);

    static const int baseArr[6] = {3072, 3755, 4011, 4075, 4091, 4095};
    static const int cntArr[6]  = {683, 256, 64, 16, 4, 1};
    int prevBase = 0, prevCnt = 3072;
    for (int l = 0; l < 6; ++l) {
        int m = cntArr[l], base = baseArr[l];
        int gy = (m + 127) / 128;
        int gy0 = (prevCnt + 127) / 128;
        int gymax = gy > gy0 ? gy : gy0;
        // z<4: split-K iou_l = (sum child h) @ Ws (+bs in split 0)
        // z>=4: split-K fw of previous level's nodes (includes leaves at l=0)
        gemm_dual<<<dim3(12, gymax, 2 * NSPLIT), NTHREADS, SMEM_BYTES>>>(
            hbuf, base, wss, bs, iou, m,
            hsp, prevBase, wfs, bf, fw + (size_t)prevBase * MEM, prevCnt);
        combine_kernel<<<m, 512>>>(ifou, iou, fw, cbuf, hbuf, hsp, base);
        prevBase = base;
        prevCnt = m;
    }

    copyout_kernel<<<1, 512>>>(hbuf, out);
}